// round 12
// baseline (speedup 1.0000x reference)
#include <cuda_runtime.h>
#include <cuda_bf16.h>
#include <cstdint>

#define NN      8192
#define C_CLS   16
#define TPB     256
#define M_TILE  128              // 8 warps x 16 rows
#define KSPLIT  16
#define KRANGE  (NN / KSPLIT)    // 512
#define NCHUNK  (KRANGE / 16)    // 32
#define NMT     (NN / M_TILE)    // 64
#define NBLK    (KSPLIT * NMT)   // 1024
#define BS_STRIDE 1040           // bytes per class-slot row: 512*2 + 16 pad (bank-clean)

// Per-block partials + completion ticket (module-load zeroed; ticket self-resets).
__device__ float g_quadp[NBLK];
__device__ float g_sp[NBLK];
__device__ float g_dHp[C_CLS][NBLK];
__device__ unsigned int g_count;

static __device__ __forceinline__ uint32_t maskw(float2 v) {
    // packed bf16x2 {0,1} mask, exact
    uint32_t lo = (v.x > 0.f) ? 0x3F80u : 0u;
    uint32_t hi = (v.y > 0.f) ? 0x3F800000u : 0u;
    return lo | hi;
}

#define MMA(dd, A0, A1, A2, A3, B0, B1)                                        \
    asm volatile(                                                              \
        "mma.sync.aligned.m16n8k16.row.col.f32.bf16.bf16.f32 "                 \
        "{%0,%1,%2,%3}, {%4,%5,%6,%7}, {%8,%9}, {%0,%1,%2,%3};"                \
        : "+f"(dd[0]), "+f"(dd[1]), "+f"(dd[2]), "+f"(dd[3])                   \
        : "r"(A0), "r"(A1), "r"(A2), "r"(A3), "r"(B0), "r"(B1))

__global__ void __launch_bounds__(TPB) mm_hmma(const float* __restrict__ A,
                                               const float* __restrict__ H,
                                               float* __restrict__ out) {
    // B slab: slots 0-15 = bf16 hi of H[kb..kb+512), slots 16-31 = bf16 lo.
    __shared__ __align__(16) unsigned char smB[32 * BS_STRIDE];   // 33280 B
    __shared__ float s_dH[C_CLS];
    __shared__ float s_quad, s_s;
    __shared__ int s_last;

    const int t = threadIdx.x, lane = t & 31, wid = t >> 5;
    const int g = lane >> 2, tq = lane & 3;    // groupID, threadID-in-group
    const int kb = blockIdx.x * KRANGE;
    const int m0 = blockIdx.y * M_TILE;

    if (t < C_CLS) s_dH[t] = 0.f;
    if (t == 0) { s_quad = 0.f; s_s = 0.f; s_last = 0; }

    // ---- Fill B slab: H rows [kb, kb+512) split hi/lo bf16, class-major ----
    for (int idx = t; idx < KRANGE * C_CLS; idx += TPB) {
        int j = idx >> 4, c = idx & 15;            // coalesced H reads
        float v = H[(size_t)(kb + j) * C_CLS + c];
        __nv_bfloat16 h = __float2bfloat16(v);
        __nv_bfloat16 e = __float2bfloat16(v - __bfloat162float(h));
        *reinterpret_cast<__nv_bfloat16*>(smB + c * BS_STRIDE + 2 * j) = h;
        *reinterpret_cast<__nv_bfloat16*>(smB + (16 + c) * BS_STRIDE + 2 * j) = e;
    }
    __syncthreads();

    // D accumulators: n-chunks 0,1 = hi classes 0-7 / 8-15; 2,3 = lo; 4 = ones col
    float d0[4] = {0,0,0,0}, d1[4] = {0,0,0,0}, d2[4] = {0,0,0,0},
          d3[4] = {0,0,0,0}, d4[4] = {0,0,0,0};
    const uint32_t bon = (g == 0) ? 0x3F803F80u : 0u;   // ones column (n==0)

    // A fragment source: rows (m0+wid*16+g, +8), col pairs (tq*2, +8) per k-chunk
    const float* ap = A + (size_t)(m0 + wid * 16 + g) * NN + kb + tq * 2;

    #pragma unroll 2
    for (int ch = 0; ch < NCHUNK; ch++) {
        const float* p = ap + ch * 16;
        float2 v00 = __ldg(reinterpret_cast<const float2*>(p));
        float2 v10 = __ldg(reinterpret_cast<const float2*>(p + 8 * NN));
        float2 v01 = __ldg(reinterpret_cast<const float2*>(p + 8));
        float2 v11 = __ldg(reinterpret_cast<const float2*>(p + 8 * NN + 8));
        uint32_t a0 = maskw(v00), a1 = maskw(v10), a2 = maskw(v01), a3 = maskw(v11);

        const unsigned char* bb = smB + (ch * 16 + tq * 2) * 2;
        uint32_t b00 = *reinterpret_cast<const uint32_t*>(bb + g * BS_STRIDE);
        uint32_t b01 = *reinterpret_cast<const uint32_t*>(bb + g * BS_STRIDE + 16);
        uint32_t b10 = *reinterpret_cast<const uint32_t*>(bb + (8 + g) * BS_STRIDE);
        uint32_t b11 = *reinterpret_cast<const uint32_t*>(bb + (8 + g) * BS_STRIDE + 16);
        uint32_t b20 = *reinterpret_cast<const uint32_t*>(bb + (16 + g) * BS_STRIDE);
        uint32_t b21 = *reinterpret_cast<const uint32_t*>(bb + (16 + g) * BS_STRIDE + 16);
        uint32_t b30 = *reinterpret_cast<const uint32_t*>(bb + (24 + g) * BS_STRIDE);
        uint32_t b31 = *reinterpret_cast<const uint32_t*>(bb + (24 + g) * BS_STRIDE + 16);

        MMA(d0, a0, a1, a2, a3, b00, b01);
        MMA(d1, a0, a1, a2, a3, b10, b11);
        MMA(d2, a0, a1, a2, a3, b20, b21);
        MMA(d3, a0, a1, a2, a3, b30, b31);
        MMA(d4, a0, a1, a2, a3, bon, bon);
    }

    // ---- Epilogue from D fragments ----
    // D element map: d[0]=(row g, col q), d[1]=(g, q+1), d[2]=(g+8, q), d[3]=(g+8, q+1)
    const int q = 2 * tq;
    const int r0 = m0 + wid * 16 + g, r1 = r0 + 8;
    // X = Xhi + Xlo per class
    float X00 = d0[0] + d2[0], X01 = d0[1] + d2[1];   // row r0, classes q, q+1
    float X02 = d1[0] + d3[0], X03 = d1[1] + d3[1];   // row r0, classes 8+q, 9+q
    float X10 = d0[2] + d2[2], X11 = d0[3] + d2[3];   // row r1
    float X12 = d1[2] + d3[2], X13 = d1[3] + d3[3];

    const float* H0 = H + (size_t)r0 * C_CLS;
    const float* H1 = H + (size_t)r1 * C_CLS;
    float qv = H0[q] * X00 + H0[q + 1] * X01 + H0[8 + q] * X02 + H0[9 + q] * X03
             + H1[q] * X10 + H1[q + 1] * X11 + H1[8 + q] * X12 + H1[9 + q] * X13;
    float sv = (tq == 0) ? (d4[0] + d4[2]) : 0.f;     // ones column (col 32), rows r0,r1

    #pragma unroll
    for (int o = 16; o > 0; o >>= 1) {
        qv += __shfl_xor_sync(0xffffffffu, qv, o);
        sv += __shfl_xor_sync(0xffffffffu, sv, o);
    }
    if (lane == 0) { atomicAdd(&s_quad, qv); atomicAdd(&s_s, sv); }

    // dH_c = sum_rows X: reduce over the 8 lanes sharing each tq
    float dh0 = X00 + X10, dh1 = X01 + X11, dh2 = X02 + X12, dh3 = X03 + X13;
    #pragma unroll
    for (int o = 4; o < 32; o <<= 1) {
        dh0 += __shfl_xor_sync(0xffffffffu, dh0, o);
        dh1 += __shfl_xor_sync(0xffffffffu, dh1, o);
        dh2 += __shfl_xor_sync(0xffffffffu, dh2, o);
        dh3 += __shfl_xor_sync(0xffffffffu, dh3, o);
    }
    if (lane < 4) {
        atomicAdd(&s_dH[q], dh0);
        atomicAdd(&s_dH[q + 1], dh1);
        atomicAdd(&s_dH[8 + q], dh2);
        atomicAdd(&s_dH[9 + q], dh3);
    }
    __syncthreads();

    // ---- Publish partials, last-block ticket ----
    const int bid = blockIdx.y * gridDim.x + blockIdx.x;
    if (t == 0) { g_quadp[bid] = s_quad; g_sp[bid] = s_s; }
    if (t < C_CLS) g_dHp[t][bid] = s_dH[t];
    __threadfence();
    __syncthreads();
    if (t == 0) {
        unsigned int ticket = atomicAdd(&g_count, 1u);
        s_last = (ticket == NBLK - 1);
    }
    __syncthreads();
    if (!s_last) return;

    // ---- Last block: final reduction over all 1024 partials ----
    __threadfence();
    double* r_acc = reinterpret_cast<double*>(smB);   // reuse B slab
    if (t < C_CLS + 2) r_acc[t] = 0.0;
    __syncthreads();

    double lq = 0.0, ls = 0.0, ldh[C_CLS];
    #pragma unroll
    for (int c = 0; c < C_CLS; c++) ldh[c] = 0.0;
    for (int slot = t; slot < NBLK; slot += TPB) {    // coalesced SoA reads
        lq += (double)g_quadp[slot];
        ls += (double)g_sp[slot];
        #pragma unroll
        for (int c = 0; c < C_CLS; c++) ldh[c] += (double)g_dHp[c][slot];
    }
    #pragma unroll
    for (int o = 16; o > 0; o >>= 1) {
        lq += __shfl_xor_sync(0xffffffffu, lq, o);
        ls += __shfl_xor_sync(0xffffffffu, ls, o);
        #pragma unroll
        for (int c = 0; c < C_CLS; c++)
            ldh[c] += __shfl_xor_sync(0xffffffffu, ldh[c], o);
    }
    if (lane == 0) {
        atomicAdd(&r_acc[0], lq);
        atomicAdd(&r_acc[1], ls);
        #pragma unroll
        for (int c = 0; c < C_CLS; c++) atomicAdd(&r_acc[2 + c], ldh[c]);
    }
    __syncthreads();
    if (t == 0) {
        double quad = r_acc[0], s = r_acc[1], dd = 0.0;
        #pragma unroll
        for (int c = 0; c < C_CLS; c++) dd += r_acc[2 + c] * r_acc[2 + c];
        out[0] = (float)((quad - dd / s) / s);
        g_count = 0;   // reset for graph replay
    }
}

extern "C" void kernel_launch(void* const* d_in, const int* in_sizes, int n_in,
                              void* d_out, int out_size) {
    const float* H = nullptr;
    const float* A = nullptr;
    for (int i = 0; i < n_in; i++) {
        if (in_sizes[i] == NN * C_CLS)   H = (const float*)d_in[i];
        else if (in_sizes[i] == NN * NN) A = (const float*)d_in[i];
    }
    dim3 grid(KSPLIT, NMT);
    mm_hmma<<<grid, TPB>>>(A, H, (float*)d_out);
}

// round 13
// speedup vs baseline: 1.0246x; 1.0246x over previous
#include <cuda_runtime.h>
#include <cuda_bf16.h>
#include <cstdint>

#define NN      8192
#define C_CLS   16
#define TPB     256
#define M_TILE  128              // 8 warps x 16 rows
#define KSPLIT  16
#define KRANGE  (NN / KSPLIT)    // 512
#define NCHUNK  (KRANGE / 16)    // 32
#define NMT     (NN / M_TILE)    // 64
#define NBLK    (KSPLIT * NMT)   // 1024
#define BS_STRIDE 1040           // bytes per class-slot row: 512*2 + 16 pad (bank-clean)

// Per-block partials + completion ticket (module-load zeroed; ticket self-resets).
__device__ float g_quadp[NBLK];
__device__ float g_sp[NBLK];
__device__ float g_dHp[C_CLS][NBLK];
__device__ unsigned int g_count;

static __device__ __forceinline__ uint32_t maskw(float2 v) {
    // packed bf16x2 {0,1} mask, exact
    uint32_t lo = (v.x > 0.f) ? 0x3F80u : 0u;
    uint32_t hi = (v.y > 0.f) ? 0x3F800000u : 0u;
    return lo | hi;
}

#define MMA(dd, A0, A1, A2, A3, B0, B1)                                        \
    asm volatile(                                                              \
        "mma.sync.aligned.m16n8k16.row.col.f32.bf16.bf16.f32 "                 \
        "{%0,%1,%2,%3}, {%4,%5,%6,%7}, {%8,%9}, {%0,%1,%2,%3};"                \
        : "+f"(dd[0]), "+f"(dd[1]), "+f"(dd[2]), "+f"(dd[3])                   \
        : "r"(A0), "r"(A1), "r"(A2), "r"(A3), "r"(B0), "r"(B1))

__global__ void __launch_bounds__(TPB) mm_hmma(const float* __restrict__ A,
                                               const float* __restrict__ H,
                                               float* __restrict__ out) {
    // B slab: slots 0-15 = bf16 hi of H[kb..kb+512), slots 16-31 = bf16 lo.
    __shared__ __align__(16) unsigned char smB[32 * BS_STRIDE];   // 33280 B
    __shared__ float s_dH[C_CLS];
    __shared__ float s_quad, s_s;
    __shared__ int s_last;

    const int t = threadIdx.x, lane = t & 31, wid = t >> 5;
    const int g = lane >> 2, tq = lane & 3;    // groupID, threadID-in-group
    const int kb = blockIdx.x * KRANGE;
    const int m0 = blockIdx.y * M_TILE;

    if (t < C_CLS) s_dH[t] = 0.f;
    if (t == 0) { s_quad = 0.f; s_s = 0.f; s_last = 0; }

    // ---- Fill B slab: H rows [kb, kb+512) split hi/lo bf16, class-major ----
    for (int idx = t; idx < KRANGE * C_CLS; idx += TPB) {
        int j = idx >> 4, c = idx & 15;            // coalesced H reads
        float v = H[(size_t)(kb + j) * C_CLS + c];
        __nv_bfloat16 h = __float2bfloat16(v);
        __nv_bfloat16 e = __float2bfloat16(v - __bfloat162float(h));
        *reinterpret_cast<__nv_bfloat16*>(smB + c * BS_STRIDE + 2 * j) = h;
        *reinterpret_cast<__nv_bfloat16*>(smB + (16 + c) * BS_STRIDE + 2 * j) = e;
    }
    __syncthreads();

    // D accumulators: n-chunks 0,1 = hi classes 0-7 / 8-15; 2,3 = lo; 4 = ones col
    float d0[4] = {0,0,0,0}, d1[4] = {0,0,0,0}, d2[4] = {0,0,0,0},
          d3[4] = {0,0,0,0}, d4[4] = {0,0,0,0};
    const uint32_t bon = (g == 0) ? 0x3F803F80u : 0u;   // ones column (n==0)

    // A fragment source: rows (m0+wid*16+g, +8), col pairs (tq*2, +8) per k-chunk
    const float* ap = A + (size_t)(m0 + wid * 16 + g) * NN + kb + tq * 2;

    #pragma unroll 2
    for (int ch = 0; ch < NCHUNK; ch++) {
        const float* p = ap + ch * 16;
        float2 v00 = __ldg(reinterpret_cast<const float2*>(p));
        float2 v10 = __ldg(reinterpret_cast<const float2*>(p + 8 * NN));
        float2 v01 = __ldg(reinterpret_cast<const float2*>(p + 8));
        float2 v11 = __ldg(reinterpret_cast<const float2*>(p + 8 * NN + 8));
        uint32_t a0 = maskw(v00), a1 = maskw(v10), a2 = maskw(v01), a3 = maskw(v11);

        const unsigned char* bb = smB + (ch * 16 + tq * 2) * 2;
        uint32_t b00 = *reinterpret_cast<const uint32_t*>(bb + g * BS_STRIDE);
        uint32_t b01 = *reinterpret_cast<const uint32_t*>(bb + g * BS_STRIDE + 16);
        uint32_t b10 = *reinterpret_cast<const uint32_t*>(bb + (8 + g) * BS_STRIDE);
        uint32_t b11 = *reinterpret_cast<const uint32_t*>(bb + (8 + g) * BS_STRIDE + 16);
        uint32_t b20 = *reinterpret_cast<const uint32_t*>(bb + (16 + g) * BS_STRIDE);
        uint32_t b21 = *reinterpret_cast<const uint32_t*>(bb + (16 + g) * BS_STRIDE + 16);
        uint32_t b30 = *reinterpret_cast<const uint32_t*>(bb + (24 + g) * BS_STRIDE);
        uint32_t b31 = *reinterpret_cast<const uint32_t*>(bb + (24 + g) * BS_STRIDE + 16);

        MMA(d0, a0, a1, a2, a3, b00, b01);
        MMA(d1, a0, a1, a2, a3, b10, b11);
        MMA(d2, a0, a1, a2, a3, b20, b21);
        MMA(d3, a0, a1, a2, a3, b30, b31);
        MMA(d4, a0, a1, a2, a3, bon, bon);
    }

    // ---- Epilogue from D fragments ----
    // D element map: d[0]=(row g, col q), d[1]=(g, q+1), d[2]=(g+8, q), d[3]=(g+8, q+1)
    const int q = 2 * tq;
    const int r0 = m0 + wid * 16 + g, r1 = r0 + 8;
    // X = Xhi + Xlo per class
    float X00 = d0[0] + d2[0], X01 = d0[1] + d2[1];   // row r0, classes q, q+1
    float X02 = d1[0] + d3[0], X03 = d1[1] + d3[1];   // row r0, classes 8+q, 9+q
    float X10 = d0[2] + d2[2], X11 = d0[3] + d2[3];   // row r1
    float X12 = d1[2] + d3[2], X13 = d1[3] + d3[3];

    const float* H0 = H + (size_t)r0 * C_CLS;
    const float* H1 = H + (size_t)r1 * C_CLS;
    float qv = H0[q] * X00 + H0[q + 1] * X01 + H0[8 + q] * X02 + H0[9 + q] * X03
             + H1[q] * X10 + H1[q + 1] * X11 + H1[8 + q] * X12 + H1[9 + q] * X13;
    float sv = (tq == 0) ? (d4[0] + d4[2]) : 0.f;     // ones column (col 32), rows r0,r1

    #pragma unroll
    for (int o = 16; o > 0; o >>= 1) {
        qv += __shfl_xor_sync(0xffffffffu, qv, o);
        sv += __shfl_xor_sync(0xffffffffu, sv, o);
    }
    if (lane == 0) { atomicAdd(&s_quad, qv); atomicAdd(&s_s, sv); }

    // dH_c = sum_rows X: reduce over the 8 lanes sharing each tq
    float dh0 = X00 + X10, dh1 = X01 + X11, dh2 = X02 + X12, dh3 = X03 + X13;
    #pragma unroll
    for (int o = 4; o < 32; o <<= 1) {
        dh0 += __shfl_xor_sync(0xffffffffu, dh0, o);
        dh1 += __shfl_xor_sync(0xffffffffu, dh1, o);
        dh2 += __shfl_xor_sync(0xffffffffu, dh2, o);
        dh3 += __shfl_xor_sync(0xffffffffu, dh3, o);
    }
    if (lane < 4) {
        atomicAdd(&s_dH[q], dh0);
        atomicAdd(&s_dH[q + 1], dh1);
        atomicAdd(&s_dH[8 + q], dh2);
        atomicAdd(&s_dH[9 + q], dh3);
    }
    __syncthreads();

    // ---- Publish partials, last-block ticket ----
    const int bid = blockIdx.y * gridDim.x + blockIdx.x;
    if (t == 0) { g_quadp[bid] = s_quad; g_sp[bid] = s_s; }
    if (t < C_CLS) g_dHp[t][bid] = s_dH[t];
    __threadfence();
    __syncthreads();
    if (t == 0) {
        unsigned int ticket = atomicAdd(&g_count, 1u);
        s_last = (ticket == NBLK - 1);
    }
    __syncthreads();
    if (!s_last) return;

    // ---- Last block: final reduction over all 1024 partials ----
    __threadfence();
    double* r_acc = reinterpret_cast<double*>(smB);   // reuse B slab
    if (t < C_CLS + 2) r_acc[t] = 0.0;
    __syncthreads();

    double lq = 0.0, ls = 0.0, ldh[C_CLS];
    #pragma unroll
    for (int c = 0; c < C_CLS; c++) ldh[c] = 0.0;
    for (int slot = t; slot < NBLK; slot += TPB) {    // coalesced SoA reads
        lq += (double)g_quadp[slot];
        ls += (double)g_sp[slot];
        #pragma unroll
        for (int c = 0; c < C_CLS; c++) ldh[c] += (double)g_dHp[c][slot];
    }
    #pragma unroll
    for (int o = 16; o > 0; o >>= 1) {
        lq += __shfl_xor_sync(0xffffffffu, lq, o);
        ls += __shfl_xor_sync(0xffffffffu, ls, o);
        #pragma unroll
        for (int c = 0; c < C_CLS; c++)
            ldh[c] += __shfl_xor_sync(0xffffffffu, ldh[c], o);
    }
    if (lane == 0) {
        atomicAdd(&r_acc[0], lq);
        atomicAdd(&r_acc[1], ls);
        #pragma unroll
        for (int c = 0; c < C_CLS; c++) atomicAdd(&r_acc[2 + c], ldh[c]);
    }
    __syncthreads();
    if (t == 0) {
        double quad = r_acc[0], s = r_acc[1], dd = 0.0;
        #pragma unroll
        for (int c = 0; c < C_CLS; c++) dd += r_acc[2 + c] * r_acc[2 + c];
        out[0] = (float)((quad - dd / s) / s);
        g_count = 0;   // reset for graph replay
    }
}

extern "C" void kernel_launch(void* const* d_in, const int* in_sizes, int n_in,
                              void* d_out, int out_size) {
    const float* H = nullptr;
    const float* A = nullptr;
    for (int i = 0; i < n_in; i++) {
        if (in_sizes[i] == NN * C_CLS)   H = (const float*)d_in[i];
        else if (in_sizes[i] == NN * NN) A = (const float*)d_in[i];
    }
    dim3 grid(KSPLIT, NMT);
    mm_hmma<<<grid, TPB>>>(A, H, (float*)d_out);
}